// round 6
// baseline (speedup 1.0000x reference)
#include <cuda_runtime.h>

#define DIM   768
#define NEXP  8
#define PARTS 4                 // threads cooperating per token
#define DPP   (DIM / PARTS / 4) // float4 iterations per part = 48
#define TPB   256

// Packed fp32x2 math (Blackwell): one instruction, two fp32 FMAs.
__device__ __forceinline__ unsigned long long ffma2(unsigned long long a,
                                                    unsigned long long b,
                                                    unsigned long long c) {
    unsigned long long d;
    asm("fma.rn.f32x2 %0, %1, %2, %3;" : "=l"(d) : "l"(a), "l"(b), "l"(c));
    return d;
}
__device__ __forceinline__ unsigned long long fadd2(unsigned long long a,
                                                    unsigned long long b) {
    unsigned long long d;
    asm("add.rn.f32x2 %0, %1, %2;" : "=l"(d) : "l"(a), "l"(b));
    return d;
}

__global__ __launch_bounds__(TPB)
void Router_54932631716286_kernel(const float* __restrict__ x,
                                  const float* __restrict__ W,
                                  const float* __restrict__ b,
                                  float* __restrict__ out,
                                  int n_tokens)
{
    // W: 8 x 768 fp32 = 24 KB, broadcast-read by every token -> stage in smem.
    __shared__ float4 sW4[NEXP * DIM / 4];
    __shared__ float  sb[NEXP];

    const float4* W4 = reinterpret_cast<const float4*>(W);
    for (int i = threadIdx.x; i < NEXP * DIM / 4; i += TPB) sW4[i] = W4[i];
    if (threadIdx.x < NEXP) sb[threadIdx.x] = b[threadIdx.x];
    __syncthreads();

    int gtid = blockIdx.x * TPB + threadIdx.x;
    int tok  = gtid >> 2;       // 4 consecutive lanes share a token
    int part = gtid & 3;

    bool valid  = tok < n_tokens;
    int  tok_c  = valid ? tok : (n_tokens - 1);   // keep warp converged for shfl

    const ulonglong2* xp = reinterpret_cast<const ulonglong2*>(x + (size_t)tok_c * DIM);
    const ulonglong2* wp = reinterpret_cast<const ulonglong2*>(sW4);

    unsigned long long acc[NEXP];
#pragma unroll
    for (int e = 0; e < NEXP; e++) acc[e] = 0ull;

    // Interleaved dim slices: part p owns float4 indices {4j + p}.
    // Each warp LDG.128 covers 8 token rows x 64 contiguous bytes -> full sectors.
#pragma unroll 4
    for (int j = 0; j < DPP; j++) {
        int i = (j << 2) + part;
        ulonglong2 xv = xp[i];
#pragma unroll
        for (int e = 0; e < NEXP; e++) {
            ulonglong2 wv = wp[e * (DIM / 4) + i];   // broadcast within token groups
            acc[e] = ffma2(xv.x, wv.x, ffma2(xv.y, wv.y, acc[e]));
        }
    }

    // Reduce the 4 partial sums (consecutive lanes) via butterfly shuffles.
#pragma unroll
    for (int e = 0; e < NEXP; e++) {
        unsigned long long v = acc[e];
        v = fadd2(v, __shfl_xor_sync(0xffffffffu, v, 1));
        v = fadd2(v, __shfl_xor_sync(0xffffffffu, v, 2));
        acc[e] = v;
    }

    if (!valid || part != 0) return;

    // Unpack packed accumulators -> logits, add bias.
    float logits[NEXP];
    float m = -1e30f;
#pragma unroll
    for (int e = 0; e < NEXP; e++) {
        float lo = __uint_as_float((unsigned)(acc[e] & 0xffffffffull));
        float hi = __uint_as_float((unsigned)(acc[e] >> 32));
        logits[e] = lo + hi + sb[e];
        m = fmaxf(m, logits[e]);
    }

    // Numerically-stable softmax over 8 experts.
    float g[NEXP];
    float s = 0.f;
#pragma unroll
    for (int e = 0; e < NEXP; e++) { g[e] = __expf(logits[e] - m); s += g[e]; }
    float inv = 1.0f / s;
#pragma unroll
    for (int e = 0; e < NEXP; e++) g[e] *= inv;

    // Top-2 (strict '>' keeps lowest index on ties, matching jax.lax.top_k).
    int i1 = 0; float g1 = g[0];
#pragma unroll
    for (int e = 1; e < NEXP; e++) if (g[e] > g1) { g1 = g[e]; i1 = e; }
    int i2 = -1; float g2 = -1e30f;
#pragma unroll
    for (int e = 0; e < NEXP; e++) if (e != i1 && g[e] > g2) { g2 = g[e]; i2 = e; }

    // Output layout: tuple flattened+concatenated as fp32:
    //   [0, 2N)  top-2 gates, [2N, 4N) top-2 indices (exact integers in fp32).
    out[(size_t)tok * 2 + 0] = g1;
    out[(size_t)tok * 2 + 1] = g2;
    float* oidx = out + (size_t)2 * n_tokens;
    oidx[(size_t)tok * 2 + 0] = (float)i1;
    oidx[(size_t)tok * 2 + 1] = (float)i2;
}

extern "C" void kernel_launch(void* const* d_in, const int* in_sizes, int n_in,
                              void* d_out, int out_size) {
    const float* x = (const float*)d_in[0];
    const float* W = (const float*)d_in[1];
    const float* b = (const float*)d_in[2];
    float* out = (float*)d_out;

    int n_tokens = in_sizes[0] / DIM;          // 128*197 = 25216
    int total    = n_tokens * PARTS;
    int blocks   = (total + TPB - 1) / TPB;

    Router_54932631716286_kernel<<<blocks, TPB>>>(x, W, b, out, n_tokens);
}

// round 7
// speedup vs baseline: 1.7273x; 1.7273x over previous
#include <cuda_runtime.h>

#define DIM    768
#define NEXP   8
#define PARTS  8                      // threads cooperating per token
#define TOKS   4                      // tokens per thread (amortize W smem reads 4x)
#define JITER  (DIM / (PARTS * 4))    // float4 steps per part = 24
#define TPB    64                     // small blocks -> 788 blocks, low wave imbalance

// Packed fp32x2 math (Blackwell): one instruction, two fp32 FMAs.
__device__ __forceinline__ unsigned long long ffma2(unsigned long long a,
                                                    unsigned long long b,
                                                    unsigned long long c) {
    unsigned long long d;
    asm("fma.rn.f32x2 %0, %1, %2, %3;" : "=l"(d) : "l"(a), "l"(b), "l"(c));
    return d;
}
__device__ __forceinline__ unsigned long long fadd2(unsigned long long a,
                                                    unsigned long long b) {
    unsigned long long d;
    asm("add.rn.f32x2 %0, %1, %2;" : "=l"(d) : "l"(a), "l"(b));
    return d;
}

__global__ __launch_bounds__(TPB)
void Router_54932631716286_kernel(const float* __restrict__ x,
                                  const float* __restrict__ W,
                                  const float* __restrict__ b,
                                  float* __restrict__ out,
                                  int n_tokens)
{
    // W: 8 x 768 fp32 = 24 KB, staged in smem; read 8 LDS.128 per j serving 4 tokens.
    __shared__ float4 sW4[NEXP * DIM / 4];
    __shared__ float  sb[NEXP];

    const float4* W4 = reinterpret_cast<const float4*>(W);
    for (int i = threadIdx.x; i < NEXP * DIM / 4; i += TPB) sW4[i] = W4[i];
    if (threadIdx.x < NEXP) sb[threadIdx.x] = b[threadIdx.x];
    __syncthreads();

    int gtid  = blockIdx.x * TPB + threadIdx.x;
    int group = gtid >> 3;            // 8 consecutive lanes share a 4-token group
    int part  = gtid & 7;
    int t0    = group * TOKS;

    if (t0 >= n_tokens) return;       // whole warp exits together (group-aligned)

    // Clamped per-token row pointers (handles ragged tail safely).
    int tr0 = t0;
    int tr1 = (t0 + 1 < n_tokens) ? t0 + 1 : t0;
    int tr2 = (t0 + 2 < n_tokens) ? t0 + 2 : t0;
    int tr3 = (t0 + 3 < n_tokens) ? t0 + 3 : t0;

    const ulonglong2* xr0 = reinterpret_cast<const ulonglong2*>(x + (size_t)tr0 * DIM);
    const ulonglong2* xr1 = reinterpret_cast<const ulonglong2*>(x + (size_t)tr1 * DIM);
    const ulonglong2* xr2 = reinterpret_cast<const ulonglong2*>(x + (size_t)tr2 * DIM);
    const ulonglong2* xr3 = reinterpret_cast<const ulonglong2*>(x + (size_t)tr3 * DIM);
    const ulonglong2* wp  = reinterpret_cast<const ulonglong2*>(sW4);

    unsigned long long acc[NEXP][TOKS];
#pragma unroll
    for (int e = 0; e < NEXP; e++)
#pragma unroll
        for (int t = 0; t < TOKS; t++) acc[e][t] = 0ull;

    // Per j: 4 independent LDG.128 (each warp-instr = 4 full 128B lines: 8 parts
    // cover 128B contiguous per token row) + 8 broadcast LDS.128 + 64 FFMA2.
#pragma unroll 4
    for (int j = 0; j < JITER; j++) {
        int i = j * PARTS + part;     // float4 index within the row
        ulonglong2 x0 = xr0[i];
        ulonglong2 x1 = xr1[i];
        ulonglong2 x2 = xr2[i];
        ulonglong2 x3 = xr3[i];
#pragma unroll
        for (int e = 0; e < NEXP; e++) {
            ulonglong2 wv = wp[e * (DIM / 4) + i];   // conflict-free, group-broadcast
            acc[e][0] = ffma2(x0.x, wv.x, ffma2(x0.y, wv.y, acc[e][0]));
            acc[e][1] = ffma2(x1.x, wv.x, ffma2(x1.y, wv.y, acc[e][1]));
            acc[e][2] = ffma2(x2.x, wv.x, ffma2(x2.y, wv.y, acc[e][2]));
            acc[e][3] = ffma2(x3.x, wv.x, ffma2(x3.y, wv.y, acc[e][3]));
        }
    }

    // Reduce the 8 part-partials (consecutive lanes) via butterfly shuffles.
#pragma unroll
    for (int e = 0; e < NEXP; e++) {
#pragma unroll
        for (int t = 0; t < TOKS; t++) {
            unsigned long long v = acc[e][t];
            v = fadd2(v, __shfl_xor_sync(0xffffffffu, v, 1));
            v = fadd2(v, __shfl_xor_sync(0xffffffffu, v, 2));
            v = fadd2(v, __shfl_xor_sync(0xffffffffu, v, 4));
            acc[e][t] = v;
        }
    }

    if (part != 0) return;

    // Epilogue: one lane handles softmax + top-2 for its 4 tokens.
    float4 gv[2], iv[2];
    float* gvf = reinterpret_cast<float*>(gv);
    float* ivf = reinterpret_cast<float*>(iv);

#pragma unroll
    for (int t = 0; t < TOKS; t++) {
        float logits[NEXP];
        float m = -1e30f;
#pragma unroll
        for (int e = 0; e < NEXP; e++) {
            float lo = __uint_as_float((unsigned)(acc[e][t] & 0xffffffffull));
            float hi = __uint_as_float((unsigned)(acc[e][t] >> 32));
            logits[e] = lo + hi + sb[e];
            m = fmaxf(m, logits[e]);
        }
        float g[NEXP], s = 0.f;
#pragma unroll
        for (int e = 0; e < NEXP; e++) { g[e] = __expf(logits[e] - m); s += g[e]; }
        float inv = 1.0f / s;
#pragma unroll
        for (int e = 0; e < NEXP; e++) g[e] *= inv;

        // Top-2, strict '>' keeps lowest index on ties (matches jax.lax.top_k).
        int i1 = 0; float g1 = g[0];
#pragma unroll
        for (int e = 1; e < NEXP; e++) if (g[e] > g1) { g1 = g[e]; i1 = e; }
        int i2 = -1; float g2 = -1e30f;
#pragma unroll
        for (int e = 0; e < NEXP; e++) if (e != i1 && g[e] > g2) { g2 = g[e]; i2 = e; }

        gvf[2 * t + 0] = g1;
        gvf[2 * t + 1] = g2;
        ivf[2 * t + 0] = (float)i1;
        ivf[2 * t + 1] = (float)i2;
    }

    // Output: [0,2N) top-2 gates, [2N,4N) indices as fp32 (exact integers).
    float* og = out + (size_t)t0 * 2;                       // 32B aligned (t0 % 4 == 0)
    float* oi = out + (size_t)2 * n_tokens + (size_t)t0 * 2;
    if (t0 + TOKS <= n_tokens) {
        reinterpret_cast<float4*>(og)[0] = gv[0];
        reinterpret_cast<float4*>(og)[1] = gv[1];
        reinterpret_cast<float4*>(oi)[0] = iv[0];
        reinterpret_cast<float4*>(oi)[1] = iv[1];
    } else {
        for (int t = 0; t < TOKS && t0 + t < n_tokens; t++) {
            og[2 * t + 0] = gvf[2 * t + 0];
            og[2 * t + 1] = gvf[2 * t + 1];
            oi[2 * t + 0] = ivf[2 * t + 0];
            oi[2 * t + 1] = ivf[2 * t + 1];
        }
    }
}

extern "C" void kernel_launch(void* const* d_in, const int* in_sizes, int n_in,
                              void* d_out, int out_size) {
    const float* x = (const float*)d_in[0];
    const float* W = (const float*)d_in[1];
    const float* b = (const float*)d_in[2];
    float* out = (float*)d_out;

    int n_tokens = in_sizes[0] / DIM;                  // 128*197 = 25216
    int groups   = (n_tokens + TOKS - 1) / TOKS;       // 6304
    int threads  = groups * PARTS;                     // 50432
    int blocks   = (threads + TPB - 1) / TPB;          // 788

    Router_54932631716286_kernel<<<blocks, TPB>>>(x, W, b, out, n_tokens);
}